// round 14
// baseline (speedup 1.0000x reference)
#include <cuda_runtime.h>
#include <cuda_bf16.h>
#include <cstdint>

#define KD     128                   // payload K (bf16), dense global pitch (256B rows)
#define PITCH  272                   // smem bytes/row: 16 chunks payload + 16B pad (conflict-free)
#define TILE_B (128 * PITCH)         // 34816 B per 128-row tile

#define SM_X   0
#define SM_Y0  TILE_B
#define SM_Y1  (2 * TILE_B)
#define SM_NX  (3 * TILE_B)          // x norms: 128 floats (512B)
#define SM_NY  (3 * TILE_B + 512)    // y norms: 256 floats (1024B)
#define SMEM_TOTAL (3 * TILE_B + 1536)   // 105984 B -> 2 CTAs/SM

// bf16 copies (x pre-scaled by -2), dense pitch KD; norms separate (exact fp32)
__device__ __nv_bfloat16 g_xb[32768 * KD];
__device__ __nv_bfloat16 g_yb[32768 * KD];
__device__ float g_norms[2 * 32768];   // [0,32768): ||x||^2, [32768,65536): ||y||^2

__device__ __forceinline__ uint32_t smem_u32(const void* p) {
    uint32_t a;
    asm("{ .reg .u64 t; cvta.to.shared.u64 t, %1; cvt.u32.u64 %0, t; }" : "=r"(a) : "l"(p));
    return a;
}
__device__ __forceinline__ void cp_async16(uint32_t dst, const void* src) {
    asm volatile("cp.async.cg.shared.global [%0], [%1], 16;" :: "r"(dst), "l"(src));
}
__device__ __forceinline__ void cp_commit() {
    asm volatile("cp.async.commit_group;" ::: "memory");
}
template <int N>
__device__ __forceinline__ void cp_wait() {
    asm volatile("cp.async.wait_group %0;" :: "n"(N) : "memory");
}
__device__ __forceinline__ void ldm_x4(uint32_t* r, uint32_t addr) {
    asm volatile("ldmatrix.sync.aligned.m8n8.x4.shared.b16 {%0,%1,%2,%3}, [%4];"
                 : "=r"(r[0]), "=r"(r[1]), "=r"(r[2]), "=r"(r[3]) : "r"(addr));
}
__device__ __forceinline__ void mma_bf16(float* c, const uint32_t* a, uint32_t b0, uint32_t b1) {
    asm volatile(
        "mma.sync.aligned.m16n8k16.row.col.f32.bf16.bf16.f32 "
        "{%0,%1,%2,%3},{%4,%5,%6,%7},{%8,%9},{%0,%1,%2,%3};"
        : "+f"(c[0]), "+f"(c[1]), "+f"(c[2]), "+f"(c[3])
        : "r"(a[0]), "r"(a[1]), "r"(a[2]), "r"(a[3]), "r"(b0), "r"(b1));
}
__device__ __forceinline__ void stcs2(float* p, float a, float b) {
    asm volatile("st.global.cs.v2.f32 [%0], {%1, %2};" :: "l"(p), "f"(a), "f"(b) : "memory");
}

// One warp per input row: bf16 convert (x scaled by -2) + exact fp32 norm.
__global__ void __launch_bounds__(256)
prep_kernel(const float* __restrict__ x, const float* __restrict__ y) {
    int gw = (blockIdx.x * 256 + threadIdx.x) >> 5;
    int lane = threadIdx.x & 31;
    bool isx = gw < 32768;
    int row = isx ? gw : gw - 32768;
    const float* src = (isx ? x : y) + (size_t)row * KD;
    __nv_bfloat16* dst = (isx ? g_xb : g_yb) + (size_t)row * KD;

    float4 v = *(const float4*)(src + lane * 4);
    float s = v.x * v.x + v.y * v.y + v.z * v.z + v.w * v.w;
#pragma unroll
    for (int o = 16; o; o >>= 1) s += __shfl_xor_sync(0xffffffffu, s, o);

    float sc = isx ? -2.0f : 1.0f;
    __nv_bfloat162 p0(__float2bfloat16(v.x * sc), __float2bfloat16(v.y * sc));
    __nv_bfloat162 p1(__float2bfloat16(v.z * sc), __float2bfloat16(v.w * sc));
    uint2 pk;
    pk.x = *(uint32_t*)&p0;
    pk.y = *(uint32_t*)&p1;
    *(uint2*)(dst + lane * 4) = pk;

    if (lane == 0) g_norms[gw] = s;
}

// x tile: cooperative, dense 256B global rows -> 272B-pitch smem
__device__ __forceinline__ void load_x_async(uint32_t sdst, const __nv_bfloat16* __restrict__ g,
                                             int tid) {
    const char* gb = (const char*)g;
#pragma unroll
    for (int i = 0; i < 8; ++i) {
        int idx = i * 256 + tid;          // 2048 chunks
        int r = idx >> 4, c = idx & 15;
        cp_async16(sdst + (uint32_t)(r * PITCH + c * 16), gb + (size_t)idx * 16);
    }
}

// y slab: one warp loads 32 rows [n0w, n0w+32) of one tile — no duplication.
__device__ __forceinline__ void load_y_warp(uint32_t sdst, const __nv_bfloat16* __restrict__ g,
                                            int n0w, int lane) {
    const char* gb = (const char*)g;
#pragma unroll
    for (int i = 0; i < 16; ++i) {        // 512 chunks (32 rows x 16)
        int idx = i * 32 + lane;
        int r = idx >> 4, c = idx & 15;
        cp_async16(sdst + (uint32_t)((n0w + r) * PITCH + c * 16),
                   gb + (size_t)((n0w + r) * 256 + c * 16));
    }
}

__global__ void __launch_bounds__(256, 2)
pairwise_cost_kernel(float* __restrict__ out) {
    extern __shared__ char smem[];
    const uint32_t sb = smem_u32(smem);
    const int tid = threadIdx.x, lane = tid & 31, wid = tid >> 5;

    const int bym = blockIdx.x;   // m tile (128 rows) — fastest: co-resident CTAs share y
    const int bxn = blockIdx.y;   // n-chunk (256 wide)
    const int bz  = blockIdx.z;   // batch

    const __nv_bfloat16* xg = g_xb + (size_t)(bz * 2048 + bym * 128) * KD;
    const __nv_bfloat16* yg = g_yb + (size_t)(bz * 2048 + bxn * 256) * KD;

    // 8 warps: 2 m-groups x 4 n-groups, warp tile 64x32
    const int m0  = (wid >> 2) * 64;
    const int n0w = (wid & 3) * 32;

    // upfront loads, deduplicated; norms staged into smem too
    load_x_async(sb + SM_X, xg, tid);
    {
        const uint32_t ydst = (wid < 4) ? (sb + SM_Y0) : (sb + SM_Y1);
        const __nv_bfloat16* ysrc = (wid < 4) ? yg : (yg + 128 * KD);
        load_y_warp(ydst, ysrc, n0w, lane);
    }
    if (tid < 32) {            // x norms: 128 floats
        cp_async16(sb + SM_NX + tid * 16,
                   g_norms + bz * 2048 + bym * 128 + tid * 4);
    } else if (tid < 96) {     // y norms: 256 floats
        int i = tid - 32;
        cp_async16(sb + SM_NY + i * 16,
                   g_norms + 32768 + bz * 2048 + bxn * 256 + i * 4);
    }
    cp_commit();

    // A ldmatrix: lanes 0-15 -> rows, lanes 16-31 -> +16B (k8-15)
    uint32_t baseA[4];
#pragma unroll
    for (int mf = 0; mf < 4; ++mf)
        baseA[mf] = sb + SM_X + (uint32_t)((m0 + 16 * mf + (lane & 15)) * PITCH)
                  + ((lane & 16) ? 16u : 0u);

    // B ldmatrix (k16): octets -> {n0-7,klo},{n0-7,khi},{n8-15,klo},{n8-15,khi}
    const uint32_t bnr = (uint32_t)(n0w + ((lane >> 4) & 1) * 8 + (lane & 7));
    const uint32_t bkb = ((lane >> 3) & 1) * 16u;
    uint32_t baseB[2];
    baseB[0] = bnr * PITCH + bkb;
    baseB[1] = (bnr + 16) * PITCH + bkb;

    cp_wait<0>();                 // all of this warp's copies complete
    __syncthreads();              // everything visible CTA-wide — only barrier

    // x norms to registers (exact fp32, from smem)
    const float* sx2 = (const float*)(smem + SM_NX);
    const float* sy2 = (const float*)(smem + SM_NY);
    float x2r[8];
#pragma unroll
    for (int mf = 0; mf < 4; ++mf)
#pragma unroll
        for (int e2 = 0; e2 < 2; ++e2)
            x2r[2 * mf + e2] = sx2[m0 + 16 * mf + (lane >> 2) + 8 * e2];

    float* og = out + (size_t)bz * 2048 * 2048;

#pragma unroll 1
    for (int t = 0; t < 2; ++t) {
        const uint32_t yb = sb + ((t & 1) ? SM_Y1 : SM_Y0);

        float c[4][4][4] = {};

        // ---- 8 full k16 steps (no tail) ----
#pragma unroll
        for (int kk = 0; kk < 8; ++kk) {
            uint32_t a[4][4], b[2][4];
#pragma unroll
            for (int mf = 0; mf < 4; ++mf) ldm_x4(a[mf], baseA[mf] + kk * 32u);
#pragma unroll
            for (int g = 0; g < 2; ++g)    ldm_x4(b[g], yb + baseB[g] + kk * 32u);
#pragma unroll
            for (int mf = 0; mf < 4; ++mf)
#pragma unroll
                for (int nf = 0; nf < 4; ++nf)
                    mma_bf16(c[mf][nf], a[mf],
                             b[nf >> 1][(nf & 1) * 2], b[nf >> 1][(nf & 1) * 2 + 1]);
        }

        // ---- epilogue: out = max(d + x2 + y2, 0)  (d already holds -2*x.y) ----
        const int ncol = bxn * 256 + t * 128 + n0w;
        float2 yn[4];
#pragma unroll
        for (int nf = 0; nf < 4; ++nf)
            yn[nf] = *(const float2*)&sy2[t * 128 + n0w + 8 * nf + 2 * (lane & 3)];

#pragma unroll
        for (int mf = 0; mf < 4; ++mf) {
#pragma unroll
            for (int e2 = 0; e2 < 2; ++e2) {
                int rowg = bym * 128 + m0 + 16 * mf + (lane >> 2) + 8 * e2;
                float xn = x2r[2 * mf + e2];
                float* orow = og + (size_t)rowg * 2048 + ncol;
#pragma unroll
                for (int nf = 0; nf < 4; ++nf) {
                    stcs2(&orow[8 * nf + 2 * (lane & 3)],
                          fmaxf(c[mf][nf][e2 * 2 + 0] + (xn + yn[nf].x), 0.f),
                          fmaxf(c[mf][nf][e2 * 2 + 1] + (xn + yn[nf].y), 0.f));
                }
            }
        }
    }
}

extern "C" void kernel_launch(void* const* d_in, const int* in_sizes, int n_in,
                              void* d_out, int out_size) {
    const float* x = (const float*)d_in[0];
    const float* y = (const float*)d_in[1];
    float* out = (float*)d_out;
    prep_kernel<<<8192, 256>>>(x, y);
    cudaFuncSetAttribute(pairwise_cost_kernel,
                         cudaFuncAttributeMaxDynamicSharedMemorySize, SMEM_TOTAL);
    dim3 grid(16, 8, 16);   // bym fastest: co-resident CTAs share the same y chunk
    pairwise_cost_kernel<<<grid, 256, SMEM_TOTAL>>>(out);
}

// round 15
// speedup vs baseline: 1.0756x; 1.0756x over previous
#include <cuda_runtime.h>
#include <cuda_bf16.h>
#include <cstdint>

#define KAUG   136                   // 128 payload + 4 aug + 4 zeros (bf16)
#define PITCH  272                   // bytes/row: 17x16B, conflict-free (68 words = 4 banks)
#define TILE_B (128 * PITCH)         // 34816 B per 128-row tile
#define CHUNKS (128 * 17)            // 16B chunks per tile = 2176

#define SM_X   0
#define SM_Y0  TILE_B
#define SM_Y1  (2 * TILE_B)
#define SMEM_TOTAL (3 * TILE_B)      // 104448 B -> 2 CTAs/SM

// augmented bf16 copies, dense pitch KAUG (272B rows, tile slabs contiguous)
__device__ __nv_bfloat16 g_xa[32768 * KAUG];
__device__ __nv_bfloat16 g_ya[32768 * KAUG];

__device__ __forceinline__ uint32_t smem_u32(const void* p) {
    uint32_t a;
    asm("{ .reg .u64 t; cvta.to.shared.u64 t, %1; cvt.u32.u64 %0, t; }" : "=r"(a) : "l"(p));
    return a;
}
__device__ __forceinline__ void cp_async16(uint32_t dst, const void* src) {
    asm volatile("cp.async.cg.shared.global [%0], [%1], 16;" :: "r"(dst), "l"(src));
}
__device__ __forceinline__ void cp_commit() {
    asm volatile("cp.async.commit_group;" ::: "memory");
}
template <int N>
__device__ __forceinline__ void cp_wait() {
    asm volatile("cp.async.wait_group %0;" :: "n"(N) : "memory");
}
__device__ __forceinline__ void ldm_x4(uint32_t* r, uint32_t addr) {
    asm volatile("ldmatrix.sync.aligned.m8n8.x4.shared.b16 {%0,%1,%2,%3}, [%4];"
                 : "=r"(r[0]), "=r"(r[1]), "=r"(r[2]), "=r"(r[3]) : "r"(addr));
}
__device__ __forceinline__ void ldm_x2(uint32_t* r, uint32_t addr) {
    asm volatile("ldmatrix.sync.aligned.m8n8.x2.shared.b16 {%0,%1}, [%2];"
                 : "=r"(r[0]), "=r"(r[1]) : "r"(addr));
}
__device__ __forceinline__ void mma_bf16(float* c, const uint32_t* a, uint32_t b0, uint32_t b1) {
    asm volatile(
        "mma.sync.aligned.m16n8k16.row.col.f32.bf16.bf16.f32 "
        "{%0,%1,%2,%3},{%4,%5,%6,%7},{%8,%9},{%0,%1,%2,%3};"
        : "+f"(c[0]), "+f"(c[1]), "+f"(c[2]), "+f"(c[3])
        : "r"(a[0]), "r"(a[1]), "r"(a[2]), "r"(a[3]), "r"(b0), "r"(b1));
}
__device__ __forceinline__ void mma_bf16_k8(float* c, uint32_t a0, uint32_t a1, uint32_t b0) {
    asm volatile(
        "mma.sync.aligned.m16n8k8.row.col.f32.bf16.bf16.f32 "
        "{%0,%1,%2,%3},{%4,%5},{%6},{%0,%1,%2,%3};"
        : "+f"(c[0]), "+f"(c[1]), "+f"(c[2]), "+f"(c[3])
        : "r"(a0), "r"(a1), "r"(b0));
}
__device__ __forceinline__ void stcs2(float* p, float a, float b) {
    asm volatile("st.global.cs.v2.f32 [%0], {%1, %2};" :: "l"(p), "f"(a), "f"(b) : "memory");
}

// One warp per input row: build augmented bf16 row.
// x rows: [-2x | x2h x2l 1 1 | 0 0 0 0]   y rows: [y | 1 1 y2h y2l | 0 0 0 0]
__global__ void __launch_bounds__(256)
prep_kernel(const float* __restrict__ x, const float* __restrict__ y) {
    int gw = (blockIdx.x * 256 + threadIdx.x) >> 5;
    int lane = threadIdx.x & 31;
    bool isx = gw < 32768;
    int row = isx ? gw : gw - 32768;
    const float* src = (isx ? x : y) + (size_t)row * 128;
    __nv_bfloat16* dst = (isx ? g_xa : g_ya) + (size_t)row * KAUG;

    float4 v = *(const float4*)(src + lane * 4);
    float s = v.x * v.x + v.y * v.y + v.z * v.z + v.w * v.w;
#pragma unroll
    for (int o = 16; o; o >>= 1) s += __shfl_xor_sync(0xffffffffu, s, o);

    float sc = isx ? -2.0f : 1.0f;
    __nv_bfloat162 p0(__float2bfloat16(v.x * sc), __float2bfloat16(v.y * sc));
    __nv_bfloat162 p1(__float2bfloat16(v.z * sc), __float2bfloat16(v.w * sc));
    uint2 pk;
    pk.x = *(uint32_t*)&p0;
    pk.y = *(uint32_t*)&p1;
    *(uint2*)(dst + lane * 4) = pk;

    if (lane == 0) {
        __nv_bfloat16 h = __float2bfloat16(s);
        __nv_bfloat16 l = __float2bfloat16(s - __bfloat162float(h));
        __nv_bfloat16 one = __float2bfloat16(1.0f);
        __nv_bfloat162 hl(h, l), oo(one, one);
        uint4 tail;
        if (isx) { tail.x = *(uint32_t*)&hl; tail.y = *(uint32_t*)&oo; }
        else     { tail.x = *(uint32_t*)&oo; tail.y = *(uint32_t*)&hl; }
        tail.z = 0u; tail.w = 0u;
        *(uint4*)(dst + 128) = tail;
    }
}

// x tile: cooperative (all 128 threads), identity slab copy
__device__ __forceinline__ void load_x_async(uint32_t sdst, const __nv_bfloat16* __restrict__ g,
                                             int tid) {
    const char* gb = (const char*)g;
#pragma unroll
    for (int i = 0; i < 17; ++i) {
        int idx = i * 128 + tid;          // 2176 chunks of 16B
        cp_async16(sdst + (uint32_t)idx * 16u, gb + (size_t)idx * 16);
    }
}

// y half-tile: one warp loads 64 rows [n0, n0+64) of one tile — no duplication.
__device__ __forceinline__ void load_y_warp64(uint32_t sdst, const __nv_bfloat16* __restrict__ g,
                                              int n0, int lane) {
    const char* gb = (const char*)g;
    uint32_t base = (uint32_t)(n0 * PITCH);
#pragma unroll
    for (int i = 0; i < 34; ++i) {        // 64 rows * 17 chunks = 1088 = 34*32
        uint32_t off = base + (uint32_t)(i * 32 + lane) * 16u;
        cp_async16(sdst + off, gb + off);
    }
}

__global__ void __launch_bounds__(128, 2)
pairwise_cost_kernel(float* __restrict__ out) {
    extern __shared__ char smem[];
    const uint32_t sb = smem_u32(smem);
    const int tid = threadIdx.x, lane = tid & 31, wid = tid >> 5;

    const int bym = blockIdx.x;   // m tile (128 rows) — fastest: co-resident CTAs share y
    const int bxn = blockIdx.y;   // n-chunk (256 wide)
    const int bz  = blockIdx.z;   // batch

    const __nv_bfloat16* xg = g_xa + (size_t)(bz * 2048 + bym * 128) * KAUG;
    const __nv_bfloat16* yg = g_ya + (size_t)(bz * 2048 + bxn * 256) * KAUG;

    // 4 warps: 2 m-groups x 2 n-groups, warp tile 64x64
    const int m0  = (wid >> 1) * 64;
    const int n0w = (wid & 1) * 64;

    // upfront loads, deduplicated:
    //   all warps: tid-stride share of x tile
    //   warp 0: Y0[0:64), warp 1: Y0[64:128), warp 2: Y1[0:64), warp 3: Y1[64:128)
    load_x_async(sb + SM_X, xg, tid);
    {
        const uint32_t ydst = (wid < 2) ? (sb + SM_Y0) : (sb + SM_Y1);
        const __nv_bfloat16* ysrc = (wid < 2) ? yg : (yg + 128 * KAUG);
        load_y_warp64(ydst, ysrc, (wid & 1) * 64, lane);
    }
    cp_commit();

    // A ldmatrix: lanes 0-15 -> rows, lanes 16-31 -> +16B (k8-15); 4 m-frags over 64 rows
    uint32_t baseA[4];
#pragma unroll
    for (int mf = 0; mf < 4; ++mf)
        baseA[mf] = sb + SM_X + (uint32_t)((m0 + 16 * mf + (lane & 15)) * PITCH)
                  + ((lane & 16) ? 16u : 0u);

    // B ldmatrix (k16): 4 groups of 16 n-rows each (64 total)
    uint32_t baseB[4];
    {
        const uint32_t bkb = ((lane >> 3) & 1) * 16u;
        const uint32_t bl = ((lane >> 4) & 1) * 8 + (lane & 7);
#pragma unroll
        for (int g = 0; g < 4; ++g)
            baseB[g] = (uint32_t)((n0w + g * 16 + bl) * PITCH) + bkb;
    }

    // k8 tail: A rows at +256B; B: 8 n8-octets via two ldm.x4 (rows n0w..n0w+64)
    const uint32_t tailB = (uint32_t)((n0w + ((lane >> 3) & 3) * 8 + (lane & 7)) * PITCH) + 256u;

    cp_wait<0>();                 // all of this warp's copies complete
    __syncthreads();              // everything visible CTA-wide — only barrier

    float* og = out + (size_t)bz * 2048 * 2048;

#pragma unroll 1
    for (int t = 0; t < 2; ++t) {
        const uint32_t yb = sb + ((t & 1) ? SM_Y1 : SM_Y0);

        float c[4][8][4] = {};    // 128 accumulators: 64x64 warp tile

        // ---- 8 full k16 steps: 8 ldm.x4 -> 32 HMMA (density 4.0) ----
#pragma unroll
        for (int kk = 0; kk < 8; ++kk) {
            uint32_t a[4][4], b[4][4];
#pragma unroll
            for (int mf = 0; mf < 4; ++mf) ldm_x4(a[mf], baseA[mf] + kk * 32u);
#pragma unroll
            for (int g = 0; g < 4; ++g)    ldm_x4(b[g], yb + baseB[g] + kk * 32u);
#pragma unroll
            for (int mf = 0; mf < 4; ++mf)
#pragma unroll
                for (int nf = 0; nf < 8; ++nf)
                    mma_bf16(c[mf][nf], a[mf],
                             b[nf >> 1][(nf & 1) * 2], b[nf >> 1][(nf & 1) * 2 + 1]);
        }

        // ---- k8 tail (aug columns 128..135) ----
        {
            uint32_t at[4][2], bt[2][4];
            ldm_x4(bt[0], yb + tailB);
            ldm_x4(bt[1], yb + tailB + 32u * PITCH);
#pragma unroll
            for (int mf = 0; mf < 4; ++mf)
                ldm_x2(at[mf], sb + SM_X +
                       (uint32_t)((m0 + 16 * mf + (lane & 15)) * PITCH) + 256u);
#pragma unroll
            for (int mf = 0; mf < 4; ++mf)
#pragma unroll
                for (int nf = 0; nf < 8; ++nf)
                    mma_bf16_k8(c[mf][nf], at[mf][0], at[mf][1], bt[nf >> 2][nf & 3]);
        }

        // ---- epilogue: D already equals cost; clamp + streaming stores ----
        const int ncol = bxn * 256 + t * 128 + n0w;
#pragma unroll
        for (int mf = 0; mf < 4; ++mf) {
#pragma unroll
            for (int e2 = 0; e2 < 2; ++e2) {
                int rowg = bym * 128 + m0 + 16 * mf + (lane >> 2) + 8 * e2;
                float* orow = og + (size_t)rowg * 2048 + ncol;
#pragma unroll
                for (int nf = 0; nf < 8; ++nf) {
                    stcs2(&orow[8 * nf + 2 * (lane & 3)],
                          fmaxf(c[mf][nf][e2 * 2 + 0], 0.f),
                          fmaxf(c[mf][nf][e2 * 2 + 1], 0.f));
                }
            }
        }
    }
}

extern "C" void kernel_launch(void* const* d_in, const int* in_sizes, int n_in,
                              void* d_out, int out_size) {
    const float* x = (const float*)d_in[0];
    const float* y = (const float*)d_in[1];
    float* out = (float*)d_out;
    prep_kernel<<<8192, 256>>>(x, y);
    cudaFuncSetAttribute(pairwise_cost_kernel,
                         cudaFuncAttributeMaxDynamicSharedMemorySize, SMEM_TOTAL);
    dim3 grid(16, 8, 16);   // bym fastest: co-resident CTAs share the same y chunk
    pairwise_cost_kernel<<<grid, 128, SMEM_TOTAL>>>(out);
}

// round 16
// speedup vs baseline: 1.0791x; 1.0033x over previous
#include <cuda_runtime.h>
#include <cuda_bf16.h>
#include <cstdint>

#define KAUG   136                   // 128 payload + 4 aug + 4 zeros (bf16)
#define PITCH  272                   // bytes/row: 17x16B, conflict-free (68 words = 4 banks)
#define TILE_B (128 * PITCH)         // 34816 B per 128-row tile
#define CHUNKS (128 * 17)            // 16B chunks per tile = 2176

#define SM_X   0
#define SM_Y0  TILE_B
#define SM_Y1  (2 * TILE_B)
#define SMEM_TOTAL (3 * TILE_B)      // 104448 B -> 2 CTAs/SM

// augmented bf16 copies, dense pitch KAUG (272B rows, tile slabs contiguous)
__device__ __nv_bfloat16 g_xa[32768 * KAUG];
__device__ __nv_bfloat16 g_ya[32768 * KAUG];

__device__ __forceinline__ uint32_t smem_u32(const void* p) {
    uint32_t a;
    asm("{ .reg .u64 t; cvta.to.shared.u64 t, %1; cvt.u32.u64 %0, t; }" : "=r"(a) : "l"(p));
    return a;
}
__device__ __forceinline__ void cp_async16(uint32_t dst, const void* src) {
    asm volatile("cp.async.cg.shared.global [%0], [%1], 16;" :: "r"(dst), "l"(src));
}
__device__ __forceinline__ void cp_commit() {
    asm volatile("cp.async.commit_group;" ::: "memory");
}
template <int N>
__device__ __forceinline__ void cp_wait() {
    asm volatile("cp.async.wait_group %0;" :: "n"(N) : "memory");
}
__device__ __forceinline__ void bar_sync(int id, int count) {
    asm volatile("bar.sync %0, %1;" :: "r"(id), "r"(count) : "memory");
}
__device__ __forceinline__ void ldm_x4(uint32_t* r, uint32_t addr) {
    asm volatile("ldmatrix.sync.aligned.m8n8.x4.shared.b16 {%0,%1,%2,%3}, [%4];"
                 : "=r"(r[0]), "=r"(r[1]), "=r"(r[2]), "=r"(r[3]) : "r"(addr));
}
__device__ __forceinline__ void ldm_x2(uint32_t* r, uint32_t addr) {
    asm volatile("ldmatrix.sync.aligned.m8n8.x2.shared.b16 {%0,%1}, [%2];"
                 : "=r"(r[0]), "=r"(r[1]) : "r"(addr));
}
__device__ __forceinline__ void mma_bf16(float* c, const uint32_t* a, uint32_t b0, uint32_t b1) {
    asm volatile(
        "mma.sync.aligned.m16n8k16.row.col.f32.bf16.bf16.f32 "
        "{%0,%1,%2,%3},{%4,%5,%6,%7},{%8,%9},{%0,%1,%2,%3};"
        : "+f"(c[0]), "+f"(c[1]), "+f"(c[2]), "+f"(c[3])
        : "r"(a[0]), "r"(a[1]), "r"(a[2]), "r"(a[3]), "r"(b0), "r"(b1));
}
__device__ __forceinline__ void mma_bf16_k8(float* c, uint32_t a0, uint32_t a1, uint32_t b0) {
    asm volatile(
        "mma.sync.aligned.m16n8k8.row.col.f32.bf16.bf16.f32 "
        "{%0,%1,%2,%3},{%4,%5},{%6},{%0,%1,%2,%3};"
        : "+f"(c[0]), "+f"(c[1]), "+f"(c[2]), "+f"(c[3])
        : "r"(a0), "r"(a1), "r"(b0));
}
__device__ __forceinline__ void stcs2(float* p, float a, float b) {
    asm volatile("st.global.cs.v2.f32 [%0], {%1, %2};" :: "l"(p), "f"(a), "f"(b) : "memory");
}

// One warp per input row: build augmented bf16 row.
// x rows: [-2x | x2h x2l 1 1 | 0 0 0 0]   y rows: [y | 1 1 y2h y2l | 0 0 0 0]
__global__ void __launch_bounds__(256)
prep_kernel(const float* __restrict__ x, const float* __restrict__ y) {
    int gw = (blockIdx.x * 256 + threadIdx.x) >> 5;
    int lane = threadIdx.x & 31;
    bool isx = gw < 32768;
    int row = isx ? gw : gw - 32768;
    const float* src = (isx ? x : y) + (size_t)row * 128;
    __nv_bfloat16* dst = (isx ? g_xa : g_ya) + (size_t)row * KAUG;

    float4 v = *(const float4*)(src + lane * 4);
    float s = v.x * v.x + v.y * v.y + v.z * v.z + v.w * v.w;
#pragma unroll
    for (int o = 16; o; o >>= 1) s += __shfl_xor_sync(0xffffffffu, s, o);

    float sc = isx ? -2.0f : 1.0f;
    __nv_bfloat162 p0(__float2bfloat16(v.x * sc), __float2bfloat16(v.y * sc));
    __nv_bfloat162 p1(__float2bfloat16(v.z * sc), __float2bfloat16(v.w * sc));
    uint2 pk;
    pk.x = *(uint32_t*)&p0;
    pk.y = *(uint32_t*)&p1;
    *(uint2*)(dst + lane * 4) = pk;

    if (lane == 0) {
        __nv_bfloat16 h = __float2bfloat16(s);
        __nv_bfloat16 l = __float2bfloat16(s - __bfloat162float(h));
        __nv_bfloat16 one = __float2bfloat16(1.0f);
        __nv_bfloat162 hl(h, l), oo(one, one);
        uint4 tail;
        if (isx) { tail.x = *(uint32_t*)&hl; tail.y = *(uint32_t*)&oo; }
        else     { tail.x = *(uint32_t*)&oo; tail.y = *(uint32_t*)&hl; }
        tail.z = 0u; tail.w = 0u;
        *(uint4*)(dst + 128) = tail;
    }
}

// x tile: cooperative (all 128 threads), identity slab copy
__device__ __forceinline__ void load_x_async(uint32_t sdst, const __nv_bfloat16* __restrict__ g,
                                             int tid) {
    const char* gb = (const char*)g;
#pragma unroll
    for (int i = 0; i < 17; ++i) {
        int idx = i * 128 + tid;          // 2176 chunks of 16B
        cp_async16(sdst + (uint32_t)idx * 16u, gb + (size_t)idx * 16);
    }
}

// y half-tile: one warp loads 64 rows [n0, n0+64) of one tile.
// Warps w and w^2 share the same rows; duplicated in-loop loads are benign.
__device__ __forceinline__ void load_y_warp64(uint32_t sdst, const __nv_bfloat16* __restrict__ g,
                                              int n0, int lane) {
    const char* gb = (const char*)g;
    uint32_t base = (uint32_t)(n0 * PITCH);
#pragma unroll
    for (int i = 0; i < 34; ++i) {        // 64 rows * 17 chunks = 1088 = 34*32
        uint32_t off = base + (uint32_t)(i * 32 + lane) * 16u;
        cp_async16(sdst + off, gb + off);
    }
}

__global__ void __launch_bounds__(128, 2)
pairwise_cost_kernel(float* __restrict__ out) {
    extern __shared__ char smem[];
    const uint32_t sb = smem_u32(smem);
    const int tid = threadIdx.x, lane = tid & 31, wid = tid >> 5;

    const int bym = blockIdx.x;   // m tile (128 rows) — fastest: co-resident CTAs share y
    const int bxn = blockIdx.y;   // n-chunk (512 wide)
    const int bz  = blockIdx.z;   // batch

    const __nv_bfloat16* xg = g_xa + (size_t)(bz * 2048 + bym * 128) * KAUG;
    const __nv_bfloat16* yg = g_ya + (size_t)(bz * 2048 + bxn * 512) * KAUG;

    // 4 warps: 2 m-groups x 2 n-groups, warp tile 64x64
    const int m0  = (wid >> 1) * 64;
    const int n0w = (wid & 1) * 64;
    const int pair_bar = 1 + (wid & 1);   // warps sharing a 64-row slab: {0,2}, {1,3}

    // prologue (deduplicated): all warps share x; warp 0/1 -> Y0, warp 2/3 -> Y1
    load_x_async(sb + SM_X, xg, tid);
    cp_commit();                                                  // group A (x)
    {
        const uint32_t ydst = (wid < 2) ? (sb + SM_Y0) : (sb + SM_Y1);
        const __nv_bfloat16* ysrc = (wid < 2) ? yg : (yg + 128 * KAUG);
        load_y_warp64(ydst, ysrc, n0w, lane);
    }
    cp_commit();                                                  // group B (prologue y)

    // A ldmatrix: lanes 0-15 -> rows, lanes 16-31 -> +16B (k8-15)
    uint32_t baseA[4];
#pragma unroll
    for (int mf = 0; mf < 4; ++mf)
        baseA[mf] = sb + SM_X + (uint32_t)((m0 + 16 * mf + (lane & 15)) * PITCH)
                  + ((lane & 16) ? 16u : 0u);

    // B ldmatrix (k16): 4 groups of 16 n-rows each (64 total)
    uint32_t baseB[4];
    {
        const uint32_t bkb = ((lane >> 3) & 1) * 16u;
        const uint32_t bl = ((lane >> 4) & 1) * 8 + (lane & 7);
#pragma unroll
        for (int g = 0; g < 4; ++g)
            baseB[g] = (uint32_t)((n0w + g * 16 + bl) * PITCH) + bkb;
    }

    // k8 tail: A rows at +256B; B: 8 n8-octets via two ldm.x4 (rows n0w..n0w+64)
    const uint32_t tailB = (uint32_t)((n0w + ((lane >> 3) & 3) * 8 + (lane & 7)) * PITCH) + 256u;

    cp_wait<0>();                 // this warp's prologue copies complete
    __syncthreads();              // everything visible CTA-wide — only CTA barrier

    float* og = out + (size_t)bz * 2048 * 2048;

#pragma unroll 1
    for (int t = 0; t < 4; ++t) {
        const uint32_t yb = sb + ((t & 1) ? SM_Y1 : SM_Y0);

        // in-loop prefetched groups: before t=2 need 1st prefetch, before t=3 the 2nd
        if (t == 2) cp_wait<1>();
        if (t == 3) cp_wait<0>();

        float c[4][8][4] = {};    // 128 accumulators: 64x64 warp tile

        // ---- 8 full k16 steps: 8 ldm.x4 -> 32 HMMA ----
#pragma unroll
        for (int kk = 0; kk < 8; ++kk) {
            uint32_t a[4][4], b[4][4];
#pragma unroll
            for (int mf = 0; mf < 4; ++mf) ldm_x4(a[mf], baseA[mf] + kk * 32u);
#pragma unroll
            for (int g = 0; g < 4; ++g)    ldm_x4(b[g], yb + baseB[g] + kk * 32u);
#pragma unroll
            for (int mf = 0; mf < 4; ++mf)
#pragma unroll
                for (int nf = 0; nf < 8; ++nf)
                    mma_bf16(c[mf][nf], a[mf],
                             b[nf >> 1][(nf & 1) * 2], b[nf >> 1][(nf & 1) * 2 + 1]);
        }

        // ---- k8 tail (aug columns 128..135) ----
        {
            uint32_t at[4][2], bt[2][4];
            ldm_x4(bt[0], yb + tailB);
            ldm_x4(bt[1], yb + tailB + 32u * PITCH);
#pragma unroll
            for (int mf = 0; mf < 4; ++mf)
                ldm_x2(at[mf], sb + SM_X +
                       (uint32_t)((m0 + 16 * mf + (lane & 15)) * PITCH) + 256u);
#pragma unroll
            for (int mf = 0; mf < 4; ++mf)
#pragma unroll
                for (int nf = 0; nf < 8; ++nf)
                    mma_bf16_k8(c[mf][nf], at[mf][0], at[mf][1], bt[nf >> 2][nf & 3]);
        }

        // pair-sync (slab partner finished reading), then prefetch Y[t+2]
        // into the buffer just consumed; duplicated identical writes are benign.
        if (t < 2) {
            bar_sync(pair_bar, 64);
            load_y_warp64(yb, yg + (size_t)(t + 2) * 128 * KAUG, n0w, lane);
            cp_commit();
        }

        // ---- epilogue: D already equals cost; clamp + streaming stores ----
        const int ncol = bxn * 512 + t * 128 + n0w;
#pragma unroll
        for (int mf = 0; mf < 4; ++mf) {
#pragma unroll
            for (int e2 = 0; e2 < 2; ++e2) {
                int rowg = bym * 128 + m0 + 16 * mf + (lane >> 2) + 8 * e2;
                float* orow = og + (size_t)rowg * 2048 + ncol;
#pragma unroll
                for (int nf = 0; nf < 8; ++nf) {
                    stcs2(&orow[8 * nf + 2 * (lane & 3)],
                          fmaxf(c[mf][nf][e2 * 2 + 0], 0.f),
                          fmaxf(c[mf][nf][e2 * 2 + 1], 0.f));
                }
            }
        }
    }
}

extern "C" void kernel_launch(void* const* d_in, const int* in_sizes, int n_in,
                              void* d_out, int out_size) {
    const float* x = (const float*)d_in[0];
    const float* y = (const float*)d_in[1];
    float* out = (float*)d_out;
    prep_kernel<<<8192, 256>>>(x, y);
    cudaFuncSetAttribute(pairwise_cost_kernel,
                         cudaFuncAttributeMaxDynamicSharedMemorySize, SMEM_TOTAL);
    dim3 grid(16, 4, 16);   // bym fastest: co-resident CTAs share the same y chunk
    pairwise_cost_kernel<<<grid, 128, SMEM_TOTAL>>>(out);
}